// round 2
// baseline (speedup 1.0000x reference)
#include <cuda_runtime.h>
#include <math.h>

#define NN 50000
#define NE 600000
#define DD 128

__device__ __align__(16) float g_nodeABDE[NN * 512];   // [Ax|Bx|Dx|Ex]
__device__ __align__(16) float g_eij[(size_t)NE * DD];
__device__ __align__(16) float g_num[NN * DD];
__device__ __align__(16) float g_den[NN * DD];
__device__ __align__(16) float g_t[NN * DD];
__device__ __align__(16) float g_x1[NN * DD];
__device__ __align__(16) float g_x2[NN * DD];
// [0]=e_sum [128]=e_sq [256]=x_sum [384]=x_sq [512]=n1_sum [640]=n1_sq [768]=n2_sum [896]=n2_sq
__device__ float g_stats[8 * DD];

static __device__ __forceinline__ float4 ld4(const float* p) {
    return *reinterpret_cast<const float4*>(p);
}
static __device__ __forceinline__ void st4(float* p, float4 v) {
    *reinterpret_cast<float4*>(p) = v;
}

// ===== K1: C[N,512] = x @ [WA|WB|WD|WE] + bias. 128 rows x 64 cols/block ====
__global__ __launch_bounds__(256) void k_node_gemm(
    const float* __restrict__ x,
    const float* __restrict__ WA, const float* __restrict__ bA,
    const float* __restrict__ WB, const float* __restrict__ bB,
    const float* __restrict__ WD, const float* __restrict__ bD,
    const float* __restrict__ WE, const float* __restrict__ bE)
{
    extern __shared__ float sm[];
    float* xs = sm;              // 128x128
    float* ws = sm + 16384;      // 128x64
    const int tid = threadIdx.x;
    const int rowBase = blockIdx.x * 128;
    const int cb = blockIdx.y;                 // 0..7
    const int mat = cb >> 1;
    const int lcb = (cb & 1) * 64;
    const float* W    = (mat == 0) ? WA : (mat == 1) ? WB : (mat == 2) ? WD : WE;
    const float* bias = (mat == 0) ? bA : (mat == 1) ? bB : (mat == 2) ? bD : bE;

    const float4 z4 = make_float4(0.f, 0.f, 0.f, 0.f);
    for (int t = tid; t < 128 * 32; t += 256) {
        int r = t >> 5, c4 = t & 31;
        int gr = rowBase + r;
        reinterpret_cast<float4*>(xs)[t] = (gr < NN) ? ld4(x + (size_t)gr * 128 + c4 * 4) : z4;
    }
    for (int t = tid; t < 128 * 16; t += 256) {
        int k = t >> 4, c4 = t & 15;
        reinterpret_cast<float4*>(ws)[t] = ld4(W + k * 128 + lcb + c4 * 4);
    }
    __syncthreads();

    const int tx = tid & 15, ty = tid >> 4;
    float acc[8][4];
#pragma unroll
    for (int i = 0; i < 8; i++)
#pragma unroll
        for (int j = 0; j < 4; j++) acc[i][j] = 0.f;

    const float* xrow = xs + (ty * 8) * 128;
#pragma unroll 4
    for (int k = 0; k < 128; k++) {
        float4 bv = reinterpret_cast<const float4*>(ws + k * 64)[tx];
#pragma unroll
        for (int i = 0; i < 8; i++) {
            float a = xrow[i * 128 + k];
            acc[i][0] += a * bv.x; acc[i][1] += a * bv.y;
            acc[i][2] += a * bv.z; acc[i][3] += a * bv.w;
        }
    }
    float4 bv = ld4(bias + lcb + tx * 4);
#pragma unroll
    for (int i = 0; i < 8; i++) {
        int gr = rowBase + ty * 8 + i;
        if (gr < NN) {
            st4(g_nodeABDE + (size_t)gr * 512 + cb * 64 + tx * 4,
                make_float4(acc[i][0] + bv.x, acc[i][1] + bv.y,
                            acc[i][2] + bv.z, acc[i][3] + bv.w));
        }
    }
}

// ===== K2: edge megakernel: Ce + e_ij + sigmoid + scatter + e-stats =========
__global__ __launch_bounds__(256) void k_edge(
    const float* __restrict__ e, const int* __restrict__ eidx,
    const float* __restrict__ WC, const float* __restrict__ bC)
{
    extern __shared__ float sm[];
    float* wcs  = sm;            // 128x128
    float* es   = sm + 16384;    // 64x128
    float* redS = sm + 24576;    // 16x128
    float* redQ = sm + 26624;    // 16x128
    const int tid = threadIdx.x;
    const int eb = blockIdx.x * 64;

    for (int t = tid; t < 4096; t += 256)
        reinterpret_cast<float4*>(wcs)[t] = ld4(WC + t * 4);
    for (int t = tid; t < 2048; t += 256) {
        int r = t >> 5, c4 = t & 31;
        reinterpret_cast<float4*>(es)[t] = ld4(e + (size_t)(eb + r) * 128 + c4 * 4);
    }
    __syncthreads();

    const int tx = tid & 15, ty = tid >> 4;
    float acc[4][8];
#pragma unroll
    for (int i = 0; i < 4; i++)
#pragma unroll
        for (int j = 0; j < 8; j++) acc[i][j] = 0.f;

    const float* erow = es + (ty * 4) * 128;
#pragma unroll 4
    for (int k = 0; k < 128; k++) {
        float4 b0 = reinterpret_cast<const float4*>(wcs + k * 128)[tx];
        float4 b1 = reinterpret_cast<const float4*>(wcs + k * 128)[tx + 16];
#pragma unroll
        for (int i = 0; i < 4; i++) {
            float a = erow[i * 128 + k];
            acc[i][0] += a * b0.x; acc[i][1] += a * b0.y;
            acc[i][2] += a * b0.z; acc[i][3] += a * b0.w;
            acc[i][4] += a * b1.x; acc[i][5] += a * b1.y;
            acc[i][6] += a * b1.z; acc[i][7] += a * b1.w;
        }
    }

    float4 bc0 = ld4(bC + tx * 4), bc1 = ld4(bC + 64 + tx * 4);
    float ssum[8], ssq[8];
#pragma unroll
    for (int j = 0; j < 8; j++) { ssum[j] = 0.f; ssq[j] = 0.f; }

    const float4* nb = reinterpret_cast<const float4*>(g_nodeABDE);
    float4* numb = reinterpret_cast<float4*>(g_num);
    float4* denb = reinterpret_cast<float4*>(g_den);
    float4* eijb = reinterpret_cast<float4*>(g_eij);

#pragma unroll
    for (int i = 0; i < 4; i++) {
        int eg = eb + ty * 4 + i;
        int src = eidx[eg];
        int dst = eidx[NE + eg];
#pragma unroll
        for (int cc = 0; cc < 2; cc++) {
            int c4 = tx + cc * 16;
            float4 dx = nb[(size_t)dst * 128 + 64 + c4];
            float4 ex = nb[(size_t)src * 128 + 96 + c4];
            float4 bx = nb[(size_t)src * 128 + 32 + c4];
            float4 bc = cc ? bc1 : bc0;
            float4 eij;
            eij.x = acc[i][cc * 4 + 0] + bc.x + dx.x + ex.x;
            eij.y = acc[i][cc * 4 + 1] + bc.y + dx.y + ex.y;
            eij.z = acc[i][cc * 4 + 2] + bc.z + dx.z + ex.z;
            eij.w = acc[i][cc * 4 + 3] + bc.w + dx.w + ex.w;
            eijb[(size_t)eg * 32 + c4] = eij;
            float4 sg;
            sg.x = 1.f / (1.f + __expf(-eij.x));
            sg.y = 1.f / (1.f + __expf(-eij.y));
            sg.z = 1.f / (1.f + __expf(-eij.z));
            sg.w = 1.f / (1.f + __expf(-eij.w));
            atomicAdd(numb + (size_t)dst * 32 + c4,
                      make_float4(sg.x * bx.x, sg.y * bx.y, sg.z * bx.z, sg.w * bx.w));
            atomicAdd(denb + (size_t)dst * 32 + c4, sg);
            ssum[cc * 4 + 0] += eij.x; ssq[cc * 4 + 0] += eij.x * eij.x;
            ssum[cc * 4 + 1] += eij.y; ssq[cc * 4 + 1] += eij.y * eij.y;
            ssum[cc * 4 + 2] += eij.z; ssq[cc * 4 + 2] += eij.z * eij.z;
            ssum[cc * 4 + 3] += eij.w; ssq[cc * 4 + 3] += eij.w * eij.w;
        }
    }
#pragma unroll
    for (int cc = 0; cc < 2; cc++)
#pragma unroll
        for (int j = 0; j < 4; j++) {
            redS[ty * 128 + cc * 64 + tx * 4 + j] = ssum[cc * 4 + j];
            redQ[ty * 128 + cc * 64 + tx * 4 + j] = ssq[cc * 4 + j];
        }
    __syncthreads();
    if (tid < 128) {
        float s = 0.f, q = 0.f;
#pragma unroll
        for (int t = 0; t < 16; t++) { s += redS[t * 128 + tid]; q += redQ[t * 128 + tid]; }
        atomicAdd(&g_stats[tid], s);
        atomicAdd(&g_stats[128 + tid], q);
    }
}

// ===== K3: t = Ax + num/(den+eps); x-stats ==================================
__global__ void k_node_t()
{
    const int c = threadIdx.x;
    const int r0 = blockIdx.x * 250;
    float s = 0.f, q = 0.f;
    for (int r = r0; r < r0 + 250; r++) {
        float t = g_nodeABDE[(size_t)r * 512 + c]
                + g_num[r * 128 + c] / (g_den[r * 128 + c] + 1e-6f);
        g_t[r * 128 + c] = t;
        s += t; q += t * t;
    }
    atomicAdd(&g_stats[256 + c], s);
    atomicAdd(&g_stats[384 + c], q);
}

// ===== K4: x1 = x + relu(BN_x(t)); n1-stats =================================
__global__ void k_node_x1(const float* __restrict__ x,
                          const float* __restrict__ gx, const float* __restrict__ bex)
{
    const int c = threadIdx.x;
    const int r0 = blockIdx.x * 250;
    float m = g_stats[256 + c] * (1.f / NN);
    float v = g_stats[384 + c] * (1.f / NN) - m * m;
    float sc = gx[c] * rsqrtf(v + 1e-5f);
    float sh = bex[c] - m * sc;
    float s = 0.f, q = 0.f;
    for (int r = r0; r < r0 + 250; r++) {
        float bn = g_t[r * 128 + c] * sc + sh;
        float x1 = x[(size_t)r * 128 + c] + fmaxf(bn, 0.f);
        g_x1[r * 128 + c] = x1;
        s += x1; q += x1 * x1;
    }
    atomicAdd(&g_stats[512 + c], s);
    atomicAdd(&g_stats[640 + c], q);
}

// ===== K5: FFN: h=BN_n1(x1); x2 = h + relu(h@Wf1+bf1)@Wf2 + bf2; n2-stats ===
__global__ __launch_bounds__(256) void k_ffn(
    const float* __restrict__ Wf1, const float* __restrict__ bf1,
    const float* __restrict__ Wf2, const float* __restrict__ bf2,
    const float* __restrict__ gn1, const float* __restrict__ ben1)
{
    extern __shared__ float sm[];
    float* hs   = sm;            // 64x128
    float* w1s  = sm + 8192;     // 128x64
    float* w2s  = sm + 16384;    // 64x128
    float* mids = sm + 24576;    // 64x68 padded
    float* scs  = sm + 28928;    // 128
    float* shs  = sm + 29056;    // 128
    const int tid = threadIdx.x;
    const int rb = blockIdx.x * 64;

    if (tid < 128) {
        int c = tid;
        float m = g_stats[512 + c] * (1.f / NN);
        float v = g_stats[640 + c] * (1.f / NN) - m * m;
        float sc = gn1[c] * rsqrtf(v + 1e-5f);
        scs[c] = sc;
        shs[c] = ben1[c] - m * sc;
    }
    __syncthreads();

    const float4 z4 = make_float4(0.f, 0.f, 0.f, 0.f);
    for (int t = tid; t < 2048; t += 256) {
        int r = t >> 5, c4 = t & 31;
        int gr = rb + r;
        float4 v = (gr < NN) ? ld4(g_x1 + (size_t)gr * 128 + c4 * 4) : z4;
        float4 h;
        h.x = v.x * scs[c4 * 4 + 0] + shs[c4 * 4 + 0];
        h.y = v.y * scs[c4 * 4 + 1] + shs[c4 * 4 + 1];
        h.z = v.z * scs[c4 * 4 + 2] + shs[c4 * 4 + 2];
        h.w = v.w * scs[c4 * 4 + 3] + shs[c4 * 4 + 3];
        reinterpret_cast<float4*>(hs)[t] = h;
    }

    const int tx = tid & 15, ty = tid >> 4;
    float acc2[4][8];
#pragma unroll
    for (int i = 0; i < 4; i++)
#pragma unroll
        for (int j = 0; j < 8; j++) acc2[i][j] = 0.f;

    for (int ch = 0; ch < 4; ch++) {
        __syncthreads();
        for (int t = tid; t < 2048; t += 256) {
            int k = t >> 4, c4 = t & 15;
            reinterpret_cast<float4*>(w1s)[t] = ld4(Wf1 + k * 256 + ch * 64 + c4 * 4);
        }
        for (int t = tid; t < 2048; t += 256) {
            int k = t >> 5, c4 = t & 31;
            reinterpret_cast<float4*>(w2s)[t] = ld4(Wf2 + (ch * 64 + k) * 128 + c4 * 4);
        }
        __syncthreads();

        float acc1[4][4];
#pragma unroll
        for (int i = 0; i < 4; i++)
#pragma unroll
            for (int j = 0; j < 4; j++) acc1[i][j] = 0.f;
#pragma unroll 4
        for (int k = 0; k < 128; k++) {
            float4 bv = reinterpret_cast<const float4*>(w1s + k * 64)[tx];
#pragma unroll
            for (int i = 0; i < 4; i++) {
                float a = hs[(ty * 4 + i) * 128 + k];
                acc1[i][0] += a * bv.x; acc1[i][1] += a * bv.y;
                acc1[i][2] += a * bv.z; acc1[i][3] += a * bv.w;
            }
        }
        float4 b1v = ld4(bf1 + ch * 64 + tx * 4);
#pragma unroll
        for (int i = 0; i < 4; i++) {
            mids[(ty * 4 + i) * 68 + tx * 4 + 0] = fmaxf(acc1[i][0] + b1v.x, 0.f);
            mids[(ty * 4 + i) * 68 + tx * 4 + 1] = fmaxf(acc1[i][1] + b1v.y, 0.f);
            mids[(ty * 4 + i) * 68 + tx * 4 + 2] = fmaxf(acc1[i][2] + b1v.z, 0.f);
            mids[(ty * 4 + i) * 68 + tx * 4 + 3] = fmaxf(acc1[i][3] + b1v.w, 0.f);
        }
        __syncthreads();
#pragma unroll 4
        for (int k = 0; k < 64; k++) {
            float4 b0 = reinterpret_cast<const float4*>(w2s + k * 128)[tx];
            float4 b1 = reinterpret_cast<const float4*>(w2s + k * 128)[tx + 16];
#pragma unroll
            for (int i = 0; i < 4; i++) {
                float a = mids[(ty * 4 + i) * 68 + k];
                acc2[i][0] += a * b0.x; acc2[i][1] += a * b0.y;
                acc2[i][2] += a * b0.z; acc2[i][3] += a * b0.w;
                acc2[i][4] += a * b1.x; acc2[i][5] += a * b1.y;
                acc2[i][6] += a * b1.z; acc2[i][7] += a * b1.w;
            }
        }
    }

    float4 f20 = ld4(bf2 + tx * 4), f21 = ld4(bf2 + 64 + tx * 4);
    float ls[8], lq[8];
#pragma unroll
    for (int j = 0; j < 8; j++) { ls[j] = 0.f; lq[j] = 0.f; }
#pragma unroll
    for (int i = 0; i < 4; i++) {
        int gr = rb + ty * 4 + i;
        if (gr >= NN) continue;
#pragma unroll
        for (int cc = 0; cc < 2; cc++) {
            int cbase = cc * 64 + tx * 4;
            float4 hv = ld4(hs + (ty * 4 + i) * 128 + cbase);
            float4 fb = cc ? f21 : f20;
            float4 o;
            o.x = hv.x + acc2[i][cc * 4 + 0] + fb.x;
            o.y = hv.y + acc2[i][cc * 4 + 1] + fb.y;
            o.z = hv.z + acc2[i][cc * 4 + 2] + fb.z;
            o.w = hv.w + acc2[i][cc * 4 + 3] + fb.w;
            st4(g_x2 + (size_t)gr * 128 + cbase, o);
            ls[cc * 4 + 0] += o.x; lq[cc * 4 + 0] += o.x * o.x;
            ls[cc * 4 + 1] += o.y; lq[cc * 4 + 1] += o.y * o.y;
            ls[cc * 4 + 2] += o.z; lq[cc * 4 + 2] += o.z * o.z;
            ls[cc * 4 + 3] += o.w; lq[cc * 4 + 3] += o.w * o.w;
        }
    }
#pragma unroll
    for (int cc = 0; cc < 2; cc++)
#pragma unroll
        for (int j = 0; j < 4; j++) {
            int c = cc * 64 + tx * 4 + j;
            atomicAdd(&g_stats[768 + c], ls[cc * 4 + j]);
            atomicAdd(&g_stats[896 + c], lq[cc * 4 + j]);
        }
}

// ===== K6: x_out = BN_n2(x2) ================================================
__global__ void k_out_x(float* __restrict__ out,
                        const float* __restrict__ gn2, const float* __restrict__ ben2)
{
    int idx = blockIdx.x * blockDim.x + threadIdx.x;
    if (idx >= NN * 32) return;
    int c0 = (idx & 31) * 4;
    float4 v = reinterpret_cast<const float4*>(g_x2)[idx];
    float val[4] = { v.x, v.y, v.z, v.w };
    float o[4];
#pragma unroll
    for (int j = 0; j < 4; j++) {
        int c = c0 + j;
        float m = g_stats[768 + c] * (1.f / NN);
        float var = g_stats[896 + c] * (1.f / NN) - m * m;
        o[j] = gn2[c] * (val[j] - m) * rsqrtf(var + 1e-5f) + ben2[c];
    }
    reinterpret_cast<float4*>(out)[idx] = make_float4(o[0], o[1], o[2], o[3]);
}

// ===== K7: e_out = e + relu(BN_e(e_ij)) =====================================
__global__ void k_out_e(const float* __restrict__ e, float* __restrict__ out,
                        const float* __restrict__ ge, const float* __restrict__ bee)
{
    size_t idx = (size_t)blockIdx.x * blockDim.x + threadIdx.x;
    if (idx >= (size_t)NE * 32) return;
    int c0 = ((int)(idx & 31)) * 4;
    float4 v = reinterpret_cast<const float4*>(g_eij)[idx];
    float4 ev = reinterpret_cast<const float4*>(e)[idx];
    float val[4] = { v.x, v.y, v.z, v.w };
    float res[4] = { ev.x, ev.y, ev.z, ev.w };
    float o[4];
#pragma unroll
    for (int j = 0; j < 4; j++) {
        int c = c0 + j;
        float m = g_stats[c] * (1.f / NE);
        float var = g_stats[128 + c] * (1.f / NE) - m * m;
        float bn = ge[c] * (val[j] - m) * rsqrtf(var + 1e-5f) + bee[c];
        o[j] = res[j] + fmaxf(bn, 0.f);
    }
    reinterpret_cast<float4*>(out + (size_t)NN * DD)[idx] = make_float4(o[0], o[1], o[2], o[3]);
}

// ===== launch ===============================================================
extern "C" void kernel_launch(void* const* d_in, const int* in_sizes, int n_in,
                              void* d_out, int out_size)
{
    const float* x   = (const float*)d_in[0];
    const float* e   = (const float*)d_in[1];
    const int*   eidx= (const int*)  d_in[2];
    const float* WA  = (const float*)d_in[3];  const float* bA  = (const float*)d_in[4];
    const float* WB  = (const float*)d_in[5];  const float* bB  = (const float*)d_in[6];
    const float* WC  = (const float*)d_in[7];  const float* bC  = (const float*)d_in[8];
    const float* WD  = (const float*)d_in[9];  const float* bD  = (const float*)d_in[10];
    const float* WE  = (const float*)d_in[11]; const float* bE  = (const float*)d_in[12];
    const float* gx  = (const float*)d_in[13]; const float* bex = (const float*)d_in[14];
    const float* ge  = (const float*)d_in[15]; const float* bee = (const float*)d_in[16];
    const float* Wf1 = (const float*)d_in[17]; const float* bf1 = (const float*)d_in[18];
    const float* Wf2 = (const float*)d_in[19]; const float* bf2 = (const float*)d_in[20];
    const float* gn1 = (const float*)d_in[21]; const float* ben1= (const float*)d_in[22];
    const float* gn2 = (const float*)d_in[23]; const float* ben2= (const float*)d_in[24];
    float* out = (float*)d_out;

    void *p_num, *p_den, *p_st;
    cudaGetSymbolAddress(&p_num, g_num);
    cudaGetSymbolAddress(&p_den, g_den);
    cudaGetSymbolAddress(&p_st,  g_stats);
    cudaMemsetAsync(p_num, 0, sizeof(float) * NN * DD, 0);
    cudaMemsetAsync(p_den, 0, sizeof(float) * NN * DD, 0);
    cudaMemsetAsync(p_st,  0, sizeof(float) * 8 * DD, 0);

    cudaFuncSetAttribute(k_node_gemm, cudaFuncAttributeMaxDynamicSharedMemorySize, 98304);
    cudaFuncSetAttribute(k_edge,      cudaFuncAttributeMaxDynamicSharedMemorySize, 114688);
    cudaFuncSetAttribute(k_ffn,       cudaFuncAttributeMaxDynamicSharedMemorySize, 116736);

    k_node_gemm<<<dim3(391, 8), 256, 98304>>>(x, WA, bA, WB, bB, WD, bD, WE, bE);
    k_edge<<<NE / 64, 256, 114688>>>(e, eidx, WC, bC);
    k_node_t<<<200, 128>>>();
    k_node_x1<<<200, 128>>>(x, gx, bex);
    k_ffn<<<782, 256, 116736>>>(Wf1, bf1, Wf2, bf2, gn1, ben1);
    k_out_x<<<(NN * 32 + 255) / 256, 256>>>(out, gn2, ben2);
    k_out_e<<<(int)(((size_t)NE * 32 + 255) / 256), 256>>>(e, out, ge, bee);
}